// round 8
// baseline (speedup 1.0000x reference)
#include <cuda_runtime.h>
#include <cuda_fp16.h>
#include <cstdint>

#define NTOK 16384
#define DM   1024
#define NH   16
#define HD   64
#define KD   1024

// ---------------- scratch (fp16 copies + intermediates) ----------------
__device__ __half g_hq [(size_t)NTOK * DM];
__device__ __half g_hk [(size_t)NTOK * DM];
__device__ __half g_hv [(size_t)NTOK * DM];
__device__ __half g_hWq[(size_t)DM * DM];
__device__ __half g_hWk[(size_t)DM * DM];
__device__ __half g_hWv[(size_t)DM * DM];
__device__ __half g_hWo[(size_t)DM * DM];
__device__ __half g_qh [(size_t)NTOK * DM];
__device__ __half g_kh [(size_t)NTOK * DM];
__device__ __half g_vh [(size_t)NTOK * DM];
__device__ __half g_att[(size_t)NTOK * DM];

__device__ __forceinline__ uint32_t smem_u32(const void* p) {
    uint32_t a;
    asm("{ .reg .u64 t; cvta.to.shared.u64 t, %1; cvt.u32.u64 %0, t; }" : "=r"(a) : "l"(p));
    return a;
}

// ---------------------------------------------------------------------------
// GEMM: C[M,1024] = A[M,1024] @ W[1024,1024]^T + bias
// fp16 inputs, fp16 mma accumulators promoted to fp32 once per K=64 ktile.
// BM=128 BN=256 BK=64, 256 thr, 8 warps (2x4), warp tile 64x64.
// 4-stage cp.async pipeline; XOR-swizzled 128B rows; ldmatrix.x4 frags.
// ---------------------------------------------------------------------------
#define BM 128
#define BN 256
#define BK 64
#define NKT (KD / BK)            // 16
#define NST 4
#define ASTG 16384               // bytes per A stage (128 rows x 128B)
#define BSTG 32768               // bytes per B stage (256 rows x 128B)
#define BOFF (NST * ASTG)        // 65536
#define GEMM_SMEM (NST * (ASTG + BSTG))   // 196608
#define NTHR 256

#define LDSM_X4(r0, r1, r2, r3, addr)                                           \
    asm volatile("ldmatrix.sync.aligned.m8n8.x4.shared.b16 {%0,%1,%2,%3}, [%4];" \
                 : "=r"(r0), "=r"(r1), "=r"(r2), "=r"(r3) : "r"(addr))

// fp16-accumulator mma, in-place C=D
#define MMA_F16A(dd, a, b0, b1)                                                 \
    asm volatile("mma.sync.aligned.m16n8k16.row.col.f16.f16.f16.f16 "           \
                 "{%0,%1}, {%2,%3,%4,%5}, {%6,%7}, {%0,%1};\n"                  \
                 : "+r"((dd)[0]), "+r"((dd)[1])                                 \
                 : "r"((a)[0]), "r"((a)[1]), "r"((a)[2]), "r"((a)[3]),          \
                   "r"(b0), "r"(b1))

// fp16-accumulator mma, C = 0 (starts a fresh chain, no zero-fill needed)
#define MMA_F16A_Z(dd, a, b0, b1)                                               \
    asm volatile("mma.sync.aligned.m16n8k16.row.col.f16.f16.f16.f16 "           \
                 "{%0,%1}, {%2,%3,%4,%5}, {%6,%7}, {%8,%8};\n"                  \
                 : "=r"((dd)[0]), "=r"((dd)[1])                                 \
                 : "r"((a)[0]), "r"((a)[1]), "r"((a)[2]), "r"((a)[3]),          \
                   "r"(b0), "r"(b1), "r"(0u))

#define CP_ASYNC16(dst, src) \
    asm volatile("cp.async.cg.shared.global [%0], [%1], 16;" :: "r"(dst), "l"(src))
#define CP_COMMIT() asm volatile("cp.async.commit_group;")
#define CP_WAIT2()  asm volatile("cp.async.wait_group 2;")

template <typename OutT>
__global__ __launch_bounds__(NTHR, 1)
void gemm_h(const __half* __restrict__ A, const __half* __restrict__ W,
            const float* __restrict__ bias, OutT* __restrict__ C)
{
    extern __shared__ char smem[];
    const uint32_t sb = smem_u32(smem);

    const int t    = threadIdx.x;
    const int warp = t >> 5;
    const int lane = t & 31;
    const int wm   = warp >> 2;          // 0..1  (M)
    const int wn   = warp & 3;           // 0..3  (N)
    const int m0   = blockIdx.y * BM;
    const int n0   = blockIdx.x * BN;

    auto stage = [&](int kt) {
        const int s = kt & (NST - 1);
        const uint32_t sa = sb + s * ASTG;
        const uint32_t sw = sb + BOFF + s * BSTG;
        #pragma unroll
        for (int i = 0; i < 4; i++) {            // A: 1024 16B chunks
            int id  = t + i * NTHR;
            int row = id >> 3, c16 = id & 7;
            const __half* src = A + (size_t)(m0 + row) * KD + kt * BK + c16 * 8;
            CP_ASYNC16(sa + row * 128 + ((c16 ^ (row & 7)) << 4), src);
        }
        #pragma unroll
        for (int i = 0; i < 8; i++) {            // B: 2048 16B chunks
            int id  = t + i * NTHR;
            int row = id >> 3, c16 = id & 7;
            const __half* src = W + (size_t)(n0 + row) * KD + kt * BK + c16 * 8;
            CP_ASYNC16(sw + row * 128 + ((c16 ^ (row & 7)) << 4), src);
        }
    };

    float accf[4][8][4];
    #pragma unroll
    for (int mi = 0; mi < 4; mi++)
        #pragma unroll
        for (int ni = 0; ni < 8; ni++)
            #pragma unroll
            for (int r = 0; r < 4; r++) accf[mi][ni][r] = 0.f;

    // per-lane ldmatrix addressing: lane supplies address for tile (lane>>3)
    const int tl   = lane >> 3;          // 0..3
    const int tr   = lane & 7;           // row within 8-row tile
    const int rsel = (tl & 1) * 8;       // tiles 1,3 -> +8 rows
    const int khh  = tl >> 1;            // tiles 2,3 -> high k-half

    uint32_t aRow[4], bRow[4];
    #pragma unroll
    for (int mi = 0; mi < 4; mi++) aRow[mi] = (wm * 64 + mi * 16 + rsel + tr) * 128;
    #pragma unroll
    for (int nj = 0; nj < 4; nj++) bRow[nj] = (wn * 64 + nj * 16 + rsel + tr) * 128;

    auto compute = [&](int s) {
        const uint32_t aB = sb + s * ASTG;
        const uint32_t bB = sb + BOFF + s * BSTG;
        uint32_t c16[4][8][2];               // fp16 accumulators for this ktile
        #pragma unroll
        for (int ks = 0; ks < 4; ks++) {
            const uint32_t kcx = (uint32_t)(((ks * 2 + khh) ^ tr) << 4);
            uint32_t a[4][4], bf[4][4];
            #pragma unroll
            for (int mi = 0; mi < 4; mi++)
                LDSM_X4(a[mi][0], a[mi][1], a[mi][2], a[mi][3], aB + aRow[mi] + kcx);
            #pragma unroll
            for (int nj = 0; nj < 4; nj++)
                LDSM_X4(bf[nj][0], bf[nj][1], bf[nj][2], bf[nj][3], bB + bRow[nj] + kcx);
            #pragma unroll
            for (int mi = 0; mi < 4; mi++)
                #pragma unroll
                for (int n8 = 0; n8 < 8; n8++) {
                    const int nj = n8 >> 1, hi = n8 & 1;
                    if (ks == 0) {
                        MMA_F16A_Z(c16[mi][n8], a[mi], bf[nj][hi], bf[nj][hi + 2]);
                    } else {
                        MMA_F16A(c16[mi][n8], a[mi], bf[nj][hi], bf[nj][hi + 2]);
                    }
                }
        }
        // promote this ktile's fp16 partials into fp32 accumulators
        #pragma unroll
        for (int mi = 0; mi < 4; mi++)
            #pragma unroll
            for (int n8 = 0; n8 < 8; n8++) {
                float2 p0 = __half22float2(*(__half2*)&c16[mi][n8][0]);
                float2 p1 = __half22float2(*(__half2*)&c16[mi][n8][1]);
                accf[mi][n8][0] += p0.x;
                accf[mi][n8][1] += p0.y;
                accf[mi][n8][2] += p1.x;
                accf[mi][n8][3] += p1.y;
            }
    };

    stage(0); CP_COMMIT();
    stage(1); CP_COMMIT();
    stage(2); CP_COMMIT();

    for (int kt = 0; kt < NKT; kt++) {
        CP_WAIT2();
        __syncthreads();
        if (kt + 3 < NKT) stage(kt + 3);
        CP_COMMIT();
        compute(kt & (NST - 1));
    }

    // epilogue
    const int gq = lane >> 2, tg = lane & 3;
    #pragma unroll
    for (int mi = 0; mi < 4; mi++) {
        const int r = m0 + wm * 64 + mi * 16 + gq;
        #pragma unroll
        for (int ni = 0; ni < 8; ni++) {
            const int cc = n0 + wn * 64 + ni * 8 + tg * 2;
            const float b0 = __ldg(bias + cc);
            const float b1 = __ldg(bias + cc + 1);
            if constexpr (sizeof(OutT) == 2) {
                __half2* p0 = (__half2*)((__half*)C + (size_t)r * DM + cc);
                __half2* p1 = (__half2*)((__half*)C + (size_t)(r + 8) * DM + cc);
                *p0 = __floats2half2_rn(accf[mi][ni][0] + b0, accf[mi][ni][1] + b1);
                *p1 = __floats2half2_rn(accf[mi][ni][2] + b0, accf[mi][ni][3] + b1);
            } else {
                *(float2*)((float*)C + (size_t)r * DM + cc) =
                    make_float2(accf[mi][ni][0] + b0, accf[mi][ni][1] + b1);
                *(float2*)((float*)C + (size_t)(r + 8) * DM + cc) =
                    make_float2(accf[mi][ni][2] + b0, accf[mi][ni][3] + b1);
            }
        }
    }
}

// ---------------- fp32 -> fp16 conversions (batched, MLP=4) ----------------
__global__ __launch_bounds__(256)
void cvt3(const float4* __restrict__ i0, uint2* __restrict__ o0,
          const float4* __restrict__ i1, uint2* __restrict__ o1,
          const float4* __restrict__ i2, uint2* __restrict__ o2)
{
    const float4* in;
    uint2* out;
    if (blockIdx.y == 0)      { in = i0; out = o0; }
    else if (blockIdx.y == 1) { in = i1; out = o1; }
    else                      { in = i2; out = o2; }
    int base = blockIdx.x * 1024 + threadIdx.x;
    float4 v[4];
    #pragma unroll
    for (int j = 0; j < 4; j++) v[j] = in[base + j * 256];
    #pragma unroll
    for (int j = 0; j < 4; j++) {
        __half2 h0 = __floats2half2_rn(v[j].x, v[j].y);
        __half2 h1 = __floats2half2_rn(v[j].z, v[j].w);
        out[base + j * 256] = make_uint2(*(uint32_t*)&h0, *(uint32_t*)&h1);
    }
}

__global__ __launch_bounds__(256)
void cvt4(const float4* __restrict__ i0, uint2* __restrict__ o0,
          const float4* __restrict__ i1, uint2* __restrict__ o1,
          const float4* __restrict__ i2, uint2* __restrict__ o2,
          const float4* __restrict__ i3, uint2* __restrict__ o3)
{
    const float4* in;
    uint2* out;
    if (blockIdx.y == 0)      { in = i0; out = o0; }
    else if (blockIdx.y == 1) { in = i1; out = o1; }
    else if (blockIdx.y == 2) { in = i2; out = o2; }
    else                      { in = i3; out = o3; }
    int base = blockIdx.x * 1024 + threadIdx.x;
    float4 v[4];
    #pragma unroll
    for (int j = 0; j < 4; j++) v[j] = in[base + j * 256];
    #pragma unroll
    for (int j = 0; j < 4; j++) {
        __half2 h0 = __floats2half2_rn(v[j].x, v[j].y);
        __half2 h1 = __floats2half2_rn(v[j].z, v[j].w);
        out[base + j * 256] = make_uint2(*(uint32_t*)&h0, *(uint32_t*)&h1);
    }
}

// ---------------- per-token head-mixing attention ----------------
// fp16 smem (no extra rounding: inputs already fp16), fp32 math.
#define HROW 34   // half2 words per smem row (32 data + 2 pad)

__global__ __launch_bounds__(256)
void head_attn(const __half* __restrict__ qh, const __half* __restrict__ kh,
               const __half* __restrict__ vh, __half* __restrict__ out)
{
    __shared__ uint32_t qs[NH * HROW];
    __shared__ uint32_t ks[NH * HROW];
    __shared__ uint32_t vs[NH * HROW];
    __shared__ float    sc[NH][NH + 1];

    const int tok = blockIdx.x;
    const int t   = threadIdx.x;
    const size_t base = (size_t)tok * DM;

    {
        int row = t >> 4;
        int c   = t & 15;
        const uint2* qp = (const uint2*)(qh + base + row * HD) + c;
        const uint2* kp = (const uint2*)(kh + base + row * HD) + c;
        const uint2* vp = (const uint2*)(vh + base + row * HD) + c;
        *(uint2*)&qs[row * HROW + c * 2] = *qp;
        *(uint2*)&ks[row * HROW + c * 2] = *kp;
        *(uint2*)&vs[row * HROW + c * 2] = *vp;
    }
    __syncthreads();

    {
        int h = t >> 4, g = t & 15;
        float s = 0.f;
        #pragma unroll
        for (int c = 0; c < 16; c++) {
            uint2 qa = *(const uint2*)&qs[h * HROW + c * 2];
            uint2 ka = *(const uint2*)&ks[g * HROW + c * 2];
            float2 q0 = __half22float2(*(__half2*)&qa.x);
            float2 q1 = __half22float2(*(__half2*)&qa.y);
            float2 k0 = __half22float2(*(__half2*)&ka.x);
            float2 k1 = __half22float2(*(__half2*)&ka.y);
            s += q0.x * k0.x + q0.y * k0.y + q1.x * k1.x + q1.y * k1.y;
        }
        sc[h][g] = s * 0.125f;
    }
    __syncthreads();

    if (t < NH) {
        float m = sc[t][0];
        #pragma unroll
        for (int g = 1; g < NH; g++) m = fmaxf(m, sc[t][g]);
        float e[NH], sum = 0.f;
        #pragma unroll
        for (int g = 0; g < NH; g++) { e[g] = __expf(sc[t][g] - m); sum += e[g]; }
        float inv = 1.f / sum;
        #pragma unroll
        for (int g = 0; g < NH; g++) sc[t][g] = e[g] * inv;
    }
    __syncthreads();

    {
        int h = t >> 4;
        int c = t & 15;
        float4 acc = make_float4(0.f, 0.f, 0.f, 0.f);
        #pragma unroll
        for (int g = 0; g < NH; g++) {
            float w = sc[h][g];
            uint2 va = *(const uint2*)&vs[g * HROW + c * 2];
            float2 v0 = __half22float2(*(__half2*)&va.x);
            float2 v1 = __half22float2(*(__half2*)&va.y);
            acc.x += w * v0.x; acc.y += w * v0.y;
            acc.z += w * v1.x; acc.w += w * v1.y;
        }
        __half2 h0 = __floats2half2_rn(acc.x, acc.y);
        __half2 h1 = __floats2half2_rn(acc.z, acc.w);
        *(uint2*)(out + base + h * HD + c * 4) =
            make_uint2(*(uint32_t*)&h0, *(uint32_t*)&h1);
    }
}

// ---------------------------------------------------------------------------
extern "C" void kernel_launch(void* const* d_in, const int* in_sizes, int n_in,
                              void* d_out, int out_size)
{
    const float* q  = (const float*)d_in[0];
    const float* k  = (const float*)d_in[1];
    const float* v  = (const float*)d_in[2];
    const float* Wq = (const float*)d_in[3];
    const float* bq = (const float*)d_in[4];
    const float* Wk = (const float*)d_in[5];
    const float* bk = (const float*)d_in[6];
    const float* Wv = (const float*)d_in[7];
    const float* bv = (const float*)d_in[8];
    const float* Wo = (const float*)d_in[9];
    const float* bo = (const float*)d_in[10];
    float* out = (float*)d_out;

    __half *hq, *hk, *hv, *hWq, *hWk, *hWv, *hWo, *qh, *kh, *vh, *att;
    cudaGetSymbolAddress((void**)&hq,  g_hq);
    cudaGetSymbolAddress((void**)&hk,  g_hk);
    cudaGetSymbolAddress((void**)&hv,  g_hv);
    cudaGetSymbolAddress((void**)&hWq, g_hWq);
    cudaGetSymbolAddress((void**)&hWk, g_hWk);
    cudaGetSymbolAddress((void**)&hWv, g_hWv);
    cudaGetSymbolAddress((void**)&hWo, g_hWo);
    cudaGetSymbolAddress((void**)&qh,  g_qh);
    cudaGetSymbolAddress((void**)&kh,  g_kh);
    cudaGetSymbolAddress((void**)&vh,  g_vh);
    cudaGetSymbolAddress((void**)&att, g_att);

    cudaFuncSetAttribute(gemm_h<__half>, cudaFuncAttributeMaxDynamicSharedMemorySize, GEMM_SMEM);
    cudaFuncSetAttribute(gemm_h<float>,  cudaFuncAttributeMaxDynamicSharedMemorySize, GEMM_SMEM);

    cvt3<<<dim3(4096, 3), 256>>>((const float4*)q, (uint2*)hq,
                                 (const float4*)k, (uint2*)hk,
                                 (const float4*)v, (uint2*)hv);
    cvt4<<<dim3(256, 4), 256>>>((const float4*)Wq, (uint2*)hWq,
                                (const float4*)Wk, (uint2*)hWk,
                                (const float4*)Wv, (uint2*)hWv,
                                (const float4*)Wo, (uint2*)hWo);

    dim3 gg(DM / BN, NTOK / BM);   // (4, 128)
    gemm_h<__half><<<gg, NTHR, GEMM_SMEM>>>(hq,  hWq, bq, qh);
    gemm_h<__half><<<gg, NTHR, GEMM_SMEM>>>(hk,  hWk, bk, kh);
    gemm_h<__half><<<gg, NTHR, GEMM_SMEM>>>(hv,  hWv, bv, vh);
    head_attn<<<NTOK, 256>>>(qh, kh, vh, att);
    gemm_h<float><<<gg, NTHR, GEMM_SMEM>>>(att, hWo, bo, out);
}